// round 9
// baseline (speedup 1.0000x reference)
#include <cuda_runtime.h>
#include <cuda_bf16.h>
#include <mma.h>

using namespace nvcuda;

#define NN   50000
#define EE   800000
#define GG   256
#define HH   128
#define NHID 256
#define NOUT 128

// ---------------- scratch (static device globals; no allocations) ----------------
__device__ float g_bufA[NN * HH];
__device__ float g_bufB[NN * HH];
__device__ int   g_perm[EE];
__device__ int   g_deg[NN];
__device__ int   g_offs[NN + 1];
__device__ int   g_cursor[NN];
__device__ float g_dinv[NN];
__device__ int   g_batch[NN];
__device__ float g_pool[GG * HH];
__device__ float g_cnt[GG];
__device__ float g_hid[GG * NHID];
__device__ int   g_is64;
// bf16 split weight images, row-major [k][n] (wmma matrix_b row_major layout)
__device__ __nv_bfloat16 g_Wh[3 * 16384];
__device__ __nv_bfloat16 g_Wl[3 * 16384];

__device__ __forceinline__ float4 f4zero() { return make_float4(0.f, 0.f, 0.f, 0.f); }

// split fp32 -> (hi, lo) bf16 packed pairs
__device__ __forceinline__ void split4(float4 v, uint2& hi, uint2& lo) {
    __nv_bfloat16 bx = __float2bfloat16(v.x), by = __float2bfloat16(v.y);
    __nv_bfloat16 bz = __float2bfloat16(v.z), bw = __float2bfloat16(v.w);
    hi.x = (unsigned)__bfloat16_as_ushort(bx) | ((unsigned)__bfloat16_as_ushort(by) << 16);
    hi.y = (unsigned)__bfloat16_as_ushort(bz) | ((unsigned)__bfloat16_as_ushort(bw) << 16);
    __nv_bfloat16 lx = __float2bfloat16(v.x - __bfloat162float(bx));
    __nv_bfloat16 ly = __float2bfloat16(v.y - __bfloat162float(by));
    __nv_bfloat16 lz = __float2bfloat16(v.z - __bfloat162float(bz));
    __nv_bfloat16 lw = __float2bfloat16(v.w - __bfloat162float(bw));
    lo.x = (unsigned)__bfloat16_as_ushort(lx) | ((unsigned)__bfloat16_as_ushort(ly) << 16);
    lo.y = (unsigned)__bfloat16_as_ushort(lz) | ((unsigned)__bfloat16_as_ushort(lw) << 16);
}

// ---------------- setup: zero + dtype detect + weight bf16-split prep ------------
__global__ void k_setup(const unsigned int* __restrict__ w,
                        const float* __restrict__ W0, const float* __restrict__ Wg1,
                        const float* __restrict__ Wg2) {
    int i = blockIdx.x * blockDim.x + threadIdx.x;
    if (i < NN) g_deg[i] = 0;
    if (i < GG * HH) g_pool[i] = 0.f;
    if (i < GG) g_cnt[i] = 0.f;
    if (blockIdx.x == 0) {
        __shared__ int nz;
        if (threadIdx.x == 0) nz = 0;
        __syncthreads();
        for (int t = threadIdx.x; t < 2048; t += blockDim.x)
            if (w[2 * t + 1] != 0u) nz = 1;   // benign race
        __syncthreads();
        if (threadIdx.x == 0) g_is64 = (nz == 0) ? 1 : 0;
    }
    // weight prep: row-major [k][n] bf16 hi/lo
    int p = i - 50176;
    if (p >= 0 && p < 3 * 16384) {
        int which = p / 16384, e = p % 16384;
        const float* Ws = which == 0 ? W0 : (which == 1 ? Wg1 : Wg2);
        float v = Ws[e];
        __nv_bfloat16 h = __float2bfloat16(v);
        __nv_bfloat16 l = __float2bfloat16(v - __bfloat162float(h));
        g_Wh[which * 16384 + e] = h;
        g_Wl[which * 16384 + e] = l;
    }
}

// Degree count + batch convert + per-graph node count.
__global__ void k_count(const void* __restrict__ ei, const void* __restrict__ batch) {
    int i = blockIdx.x * blockDim.x + threadIdx.x;
    int is64 = g_is64;
    if (i < EE) {
        int d = is64 ? (int)((const long long*)ei)[EE + i] : ((const int*)ei)[EE + i];
        atomicAdd(&g_deg[d], 1);
    }
    if (i < NN) {
        int b = is64 ? (int)((const long long*)batch)[i] : ((const int*)batch)[i];
        g_batch[i] = b;
        atomicAdd(&g_cnt[b], 1.f);
    }
}

// Single-block scan + dinv.
__global__ void k_scan() {
    __shared__ int sh[1024];
    int t = threadIdx.x;
    const int C = (NN + 1023) / 1024;
    int base = t * C;
    int sum = 0;
    for (int j = 0; j < C; j++) {
        int i = base + j;
        if (i < NN) sum += g_deg[i];
    }
    sh[t] = sum;
    __syncthreads();
    for (int d = 1; d < 1024; d <<= 1) {
        int v = (t >= d) ? sh[t - d] : 0;
        __syncthreads();
        sh[t] += v;
        __syncthreads();
    }
    int run = sh[t] - sum;
    if (t == 0) g_offs[0] = 0;
    for (int j = 0; j < C; j++) {
        int i = base + j;
        if (i < NN) {
            int d = g_deg[i];
            g_cursor[i] = run;
            run += d;
            g_offs[i + 1] = run;
            g_dinv[i] = rsqrtf((float)(d + 1));
        }
    }
}

__global__ void k_fill(const void* __restrict__ ei) {
    int i = blockIdx.x * blockDim.x + threadIdx.x;
    if (i < EE) {
        int s, d;
        if (g_is64) {
            const long long* p = (const long long*)ei;
            s = (int)p[i]; d = (int)p[EE + i];
        } else {
            const int* p = (const int*)ei;
            s = p[i]; d = p[EE + i];
        }
        int slot = atomicAdd(&g_cursor[d], 1);
        g_perm[slot] = s;
    }
}

// ---------------- WMMA GEMM (+optional fused GIN gather) -------------------------
// C[M,128] = act((A[M,128] @ W[128,128]) * scale? + bias?), split-bf16 (3 products),
// fp32 accumulate on tensor pipe. fused=1: A row = h[node] + sum_nbr h[nbr].
// 256 threads = 8 warps; warp grid 4(rows)x2(cols): warp tile 16 x 64.
#define AST 136     // A smem stride (bf16 elements)
#define CST 132     // epilogue smem stride (floats)

__global__ void __launch_bounds__(256)
k_wmma(const float* __restrict__ A, int widx,
       const float* __restrict__ bias, const float* __restrict__ scale,
       float* __restrict__ C, int M, int fused, int relu) {
    __shared__ __align__(16) char sm[64 * AST * 2 * 2];   // 34816 B
    __nv_bfloat16* sa_hi = (__nv_bfloat16*)sm;
    __nv_bfloat16* sa_lo = (__nv_bfloat16*)(sm + 64 * AST * 2);
    int tid = threadIdx.x, wid = tid >> 5, lane = tid & 31;
    int m0 = blockIdx.x * 64;

    // ---- A fill (split to bf16 hi/lo) ----
    if (!fused) {
        const float4* A4 = (const float4*)A;
#pragma unroll
        for (int i = 0; i < 8; i++) {
            int idx = tid + i * 256;           // 2048 float4 slots
            int r = idx >> 5, q = idx & 31;
            float4 v = (m0 + r < M) ? __ldg(&A4[(m0 + r) * 32 + q]) : f4zero();
            uint2 hi, lo;
            split4(v, hi, lo);
            *(uint2*)(sa_hi + r * AST + q * 4) = hi;
            *(uint2*)(sa_lo + r * AST + q * 4) = lo;
        }
    } else {
        const float4* h4 = (const float4*)A;
#pragma unroll 1
        for (int rr = 0; rr < 8; rr++) {
            int r = wid * 8 + rr;              // 8 warps x 8 rows = 64
            int node = m0 + r;
            float4 acc = f4zero();
            if (node < M) {
                acc = h4[node * 32 + lane];
                int s0 = g_offs[node], s1 = g_offs[node + 1];
                int j = s0;
                for (; j + 3 < s1; j += 4) {
                    int n0 = g_perm[j], n1 = g_perm[j + 1], n2 = g_perm[j + 2], n3 = g_perm[j + 3];
                    float4 u0 = h4[n0 * 32 + lane];
                    float4 u1 = h4[n1 * 32 + lane];
                    float4 u2 = h4[n2 * 32 + lane];
                    float4 u3 = h4[n3 * 32 + lane];
                    acc.x += (u0.x + u1.x) + (u2.x + u3.x);
                    acc.y += (u0.y + u1.y) + (u2.y + u3.y);
                    acc.z += (u0.z + u1.z) + (u2.z + u3.z);
                    acc.w += (u0.w + u1.w) + (u2.w + u3.w);
                }
                for (; j < s1; j++) {
                    float4 u = h4[g_perm[j] * 32 + lane];
                    acc.x += u.x; acc.y += u.y; acc.z += u.z; acc.w += u.w;
                }
            }
            uint2 hi, lo;
            split4(acc, hi, lo);
            *(uint2*)(sa_hi + r * AST + lane * 4) = hi;
            *(uint2*)(sa_lo + r * AST + lane * 4) = lo;
        }
    }
    __syncthreads();

    // ---- tensor phase: 3-product split-bf16 ----
    int wrow = wid >> 1;     // 0..3: rows wrow*16..+15
    int wcol = wid & 1;      // 0..1: cols wcol*64..+63
    wmma::fragment<wmma::accumulator, 16, 16, 16, float> facc[4];
#pragma unroll
    for (int n = 0; n < 4; n++) wmma::fill_fragment(facc[n], 0.f);

    const __nv_bfloat16* Bh = g_Wh + widx * 16384;
    const __nv_bfloat16* Bl = g_Wl + widx * 16384;

#pragma unroll 1
    for (int k = 0; k < 8; k++) {
        wmma::fragment<wmma::matrix_a, 16, 16, 16, __nv_bfloat16, wmma::row_major> ah, al;
        wmma::load_matrix_sync(ah, sa_hi + (wrow * 16) * AST + k * 16, AST);
        wmma::load_matrix_sync(al, sa_lo + (wrow * 16) * AST + k * 16, AST);
#pragma unroll
        for (int n = 0; n < 4; n++) {
            wmma::fragment<wmma::matrix_b, 16, 16, 16, __nv_bfloat16, wmma::row_major> bh, bl;
            int nc = wcol * 64 + n * 16;
            wmma::load_matrix_sync(bh, Bh + (k * 16) * 128 + nc, 128);
            wmma::load_matrix_sync(bl, Bl + (k * 16) * 128 + nc, 128);
            wmma::mma_sync(facc[n], ah, bh, facc[n]);
            wmma::mma_sync(facc[n], ah, bl, facc[n]);
            wmma::mma_sync(facc[n], al, bh, facc[n]);
        }
    }

    // ---- epilogue via smem (reuse A area) ----
    __syncthreads();
    float* cs = (float*)sm;
#pragma unroll
    for (int n = 0; n < 4; n++)
        wmma::store_matrix_sync(cs + (wrow * 16) * CST + wcol * 64 + n * 16,
                                facc[n], CST, wmma::mem_row_major);
    __syncthreads();

    const float4* b4p = (const float4*)bias;
    float4* C4 = (float4*)C;
#pragma unroll
    for (int i = 0; i < 8; i++) {
        int idx = tid + i * 256;
        int r = idx >> 5, q = idx & 31;
        int grow = m0 + r;
        if (grow < M) {
            float4 o = *(float4*)(cs + r * CST + q * 4);
            float s = scale ? scale[grow] : 1.f;
            float4 bb = f4zero();
            if (bias) bb = b4p[q];
            o.x = fmaf(o.x, s, bb.x); o.y = fmaf(o.y, s, bb.y);
            o.z = fmaf(o.z, s, bb.z); o.w = fmaf(o.w, s, bb.w);
            if (relu) {
                o.x = fmaxf(o.x, 0.f); o.y = fmaxf(o.y, 0.f);
                o.z = fmaxf(o.z, 0.f); o.w = fmaxf(o.w, 0.f);
            }
            C4[grow * 32 + q] = o;
        }
    }
}

// ---------------- GCN aggregation (standalone; h pre-scaled by dinv) -------------
__global__ void k_gcn_agg(const float* __restrict__ h, const float* __restrict__ b0,
                          float* __restrict__ out) {
    int node = blockIdx.x * 8 + (threadIdx.x >> 5);
    if (node >= NN) return;
    int lane = threadIdx.x & 31;
    const float4* h4 = (const float4*)h;

    float4 acc = h4[node * 32 + lane];
    int s0 = g_offs[node], s1 = g_offs[node + 1];
    int j = s0;
    for (; j + 3 < s1; j += 4) {
        int n0 = g_perm[j], n1 = g_perm[j + 1], n2 = g_perm[j + 2], n3 = g_perm[j + 3];
        float4 u0 = h4[n0 * 32 + lane];
        float4 u1 = h4[n1 * 32 + lane];
        float4 u2 = h4[n2 * 32 + lane];
        float4 u3 = h4[n3 * 32 + lane];
        acc.x += (u0.x + u1.x) + (u2.x + u3.x);
        acc.y += (u0.y + u1.y) + (u2.y + u3.y);
        acc.z += (u0.z + u1.z) + (u2.z + u3.z);
        acc.w += (u0.w + u1.w) + (u2.w + u3.w);
    }
    for (; j < s1; j++) {
        float4 u = h4[g_perm[j] * 32 + lane];
        acc.x += u.x; acc.y += u.y; acc.z += u.z; acc.w += u.w;
    }
    float di = g_dinv[node];
    float4 b = ((const float4*)b0)[lane];
    float4 o;
    o.x = fmaxf(fmaf(di, acc.x, b.x), 0.f);
    o.y = fmaxf(fmaf(di, acc.y, b.y), 0.f);
    o.z = fmaxf(fmaf(di, acc.z, b.z), 0.f);
    o.w = fmaxf(fmaf(di, acc.w, b.w), 0.f);
    ((float4*)out)[node * 32 + lane] = o;
}

// ---------------- mean pool: sorted batch -> run-accumulate, few atomics ---------
#define POOL_NODES 128
__global__ void k_pool(const float* __restrict__ h) {
    __shared__ int sb[POOL_NODES];
    int c = threadIdx.x;
    int n0 = blockIdx.x * POOL_NODES;
    int nend = n0 + POOL_NODES; if (nend > NN) nend = NN;
    for (int i = n0 + c; i < nend; i += 128) sb[i - n0] = g_batch[i];
    __syncthreads();

    float acc = 0.f;
    int cur = sb[0];
    for (int n = n0; n < nend; n++) {
        int g = sb[n - n0];
        if (g != cur) {
            atomicAdd(&g_pool[cur * HH + c], acc);
            acc = 0.f; cur = g;
        }
        acc += h[n * HH + c];
    }
    atomicAdd(&g_pool[cur * HH + c], acc);
}

// ---------------- head MLP ----------------
__global__ void k_head1(const float* __restrict__ Wh1, const float* __restrict__ bh1) {
    int g = blockIdx.x, c = threadIdx.x;
    float inv = 1.f / fmaxf(g_cnt[g], 1.f);
    float acc = bh1[c];
    const float* pr = &g_pool[g * HH];
#pragma unroll 8
    for (int k = 0; k < HH; k++)
        acc = fmaf(pr[k] * inv, __ldg(&Wh1[k * NHID + c]), acc);
    g_hid[g * NHID + c] = fmaxf(acc, 0.f);
}

__global__ void k_head2(const float* __restrict__ Wh2, const float* __restrict__ bh2,
                        float* __restrict__ out) {
    int g = blockIdx.x, c = threadIdx.x;
    float acc = bh2[c];
    const float* hr = &g_hid[g * NHID];
#pragma unroll 8
    for (int k = 0; k < NHID; k++)
        acc = fmaf(hr[k], __ldg(&Wh2[k * NOUT + c]), acc);
    out[g * NOUT + c] = acc;
}

// ---------------- launch ----------------
extern "C" void kernel_launch(void* const* d_in, const int* in_sizes, int n_in,
                              void* d_out, int out_size) {
    (void)in_sizes; (void)n_in; (void)out_size;
    const float* x   = (const float*)d_in[0];
    const void*  ei  = d_in[1];
    const void*  bat = d_in[2];
    const float* W0  = (const float*)d_in[3];
    const float* b0  = (const float*)d_in[4];
    const float* Wg1 = (const float*)d_in[5];
    const float* bg1 = (const float*)d_in[6];
    const float* Wg2 = (const float*)d_in[7];
    const float* bg2 = (const float*)d_in[8];
    const float* Wh1 = (const float*)d_in[9];
    const float* bh1 = (const float*)d_in[10];
    const float* Wh2 = (const float*)d_in[11];
    const float* bh2 = (const float*)d_in[12];
    float* out = (float*)d_out;

    float *bufA, *bufB, *dinv;
    cudaGetSymbolAddress((void**)&bufA, g_bufA);
    cudaGetSymbolAddress((void**)&bufB, g_bufB);
    cudaGetSymbolAddress((void**)&dinv, g_dinv);

    const int TB = 256;
    int mma_blocks = (NN + 63) / 64;     // 782
    int agg_blocks = (NN + 7) / 8;

    // 0..2: setup (+weight bf16 prep), count, scan
    k_setup<<<388, TB>>>((const unsigned int*)ei, W0, Wg1, Wg2);
    k_count<<<(EE + TB - 1) / TB, TB>>>(ei, bat);
    k_scan<<<1, 1024>>>();
    // 3: GCN transform via WMMA, row-scaled by dinv  (PROFILED LAUNCH)
    k_wmma<<<mma_blocks, 256>>>(x, 0, nullptr, dinv, bufA, NN, 0, 0);
    // 4: CSR bucket fill
    k_fill<<<(EE + TB - 1) / TB, TB>>>(ei);
    // 5: GCN aggregation (+bias+relu)
    k_gcn_agg<<<agg_blocks, 256>>>(bufA, b0, bufB);
    // 6: GIN layer 1 (fused gather + WMMA + bias + relu)
    k_wmma<<<mma_blocks, 256>>>(bufB, 1, bg1, nullptr, bufA, NN, 1, 1);
    // 7: GIN layer 2
    k_wmma<<<mma_blocks, 256>>>(bufA, 2, bg2, nullptr, bufB, NN, 1, 1);
    // 8-10: pool + head
    k_pool<<<(NN + POOL_NODES - 1) / POOL_NODES, 128>>>(bufB);
    k_head1<<<GG, NHID>>>(Wh1, bh1);
    k_head2<<<GG, NOUT>>>(Wh2, bh2, out);
}

// round 10
// speedup vs baseline: 1.3176x; 1.3176x over previous
#include <cuda_runtime.h>
#include <cuda_bf16.h>
#include <mma.h>

using namespace nvcuda;

#define NN   50000
#define EE   800000
#define GG   256
#define HH   128
#define NHID 256
#define NOUT 128

// ---------------- scratch (static device globals; no allocations) ----------------
__device__ float g_bufA[NN * HH];
__device__ float g_bufB[NN * HH];
__device__ int   g_perm[EE];
__device__ int   g_deg[NN];
__device__ int   g_offs[NN + 1];
__device__ int   g_cursor[NN];
__device__ float g_dinv[NN];
__device__ int   g_batch[NN];
__device__ float g_pool[GG * HH];
__device__ float g_cnt[GG];
__device__ float g_hid[GG * NHID];
__device__ int   g_is64;
// bf16 split weight images, row-major [k][n] (wmma matrix_b row_major layout)
__device__ __nv_bfloat16 g_Wh[3 * 16384];
__device__ __nv_bfloat16 g_Wl[3 * 16384];

__device__ __forceinline__ float4 f4zero() { return make_float4(0.f, 0.f, 0.f, 0.f); }

// split fp32 -> (hi, lo) bf16 packed pairs
__device__ __forceinline__ void split4(float4 v, uint2& hi, uint2& lo) {
    __nv_bfloat16 bx = __float2bfloat16(v.x), by = __float2bfloat16(v.y);
    __nv_bfloat16 bz = __float2bfloat16(v.z), bw = __float2bfloat16(v.w);
    hi.x = (unsigned)__bfloat16_as_ushort(bx) | ((unsigned)__bfloat16_as_ushort(by) << 16);
    hi.y = (unsigned)__bfloat16_as_ushort(bz) | ((unsigned)__bfloat16_as_ushort(bw) << 16);
    __nv_bfloat16 lx = __float2bfloat16(v.x - __bfloat162float(bx));
    __nv_bfloat16 ly = __float2bfloat16(v.y - __bfloat162float(by));
    __nv_bfloat16 lz = __float2bfloat16(v.z - __bfloat162float(bz));
    __nv_bfloat16 lw = __float2bfloat16(v.w - __bfloat162float(bw));
    lo.x = (unsigned)__bfloat16_as_ushort(lx) | ((unsigned)__bfloat16_as_ushort(ly) << 16);
    lo.y = (unsigned)__bfloat16_as_ushort(lz) | ((unsigned)__bfloat16_as_ushort(lw) << 16);
}

// ---------------- setup: zero + dtype detect + weight bf16-split prep ------------
__global__ void k_setup(const unsigned int* __restrict__ w,
                        const float* __restrict__ W0, const float* __restrict__ Wg1,
                        const float* __restrict__ Wg2) {
    int i = blockIdx.x * blockDim.x + threadIdx.x;
    if (i < NN) g_deg[i] = 0;
    if (i < GG * HH) g_pool[i] = 0.f;
    if (i < GG) g_cnt[i] = 0.f;
    if (blockIdx.x == 0) {
        __shared__ int nz;
        if (threadIdx.x == 0) nz = 0;
        __syncthreads();
        for (int t = threadIdx.x; t < 2048; t += blockDim.x)
            if (w[2 * t + 1] != 0u) nz = 1;   // benign race
        __syncthreads();
        if (threadIdx.x == 0) g_is64 = (nz == 0) ? 1 : 0;
    }
    // weight prep: row-major [k][n] bf16 hi/lo
    int p = i - 50176;
    if (p >= 0 && p < 3 * 16384) {
        int which = p / 16384, e = p % 16384;
        const float* Ws = which == 0 ? W0 : (which == 1 ? Wg1 : Wg2);
        float v = Ws[e];
        __nv_bfloat16 h = __float2bfloat16(v);
        __nv_bfloat16 l = __float2bfloat16(v - __bfloat162float(h));
        g_Wh[which * 16384 + e] = h;
        g_Wl[which * 16384 + e] = l;
    }
}

// Degree count + batch convert + per-graph node count.
__global__ void k_count(const void* __restrict__ ei, const void* __restrict__ batch) {
    int i = blockIdx.x * blockDim.x + threadIdx.x;
    int is64 = g_is64;
    if (i < EE) {
        int d = is64 ? (int)((const long long*)ei)[EE + i] : ((const int*)ei)[EE + i];
        atomicAdd(&g_deg[d], 1);
    }
    if (i < NN) {
        int b = is64 ? (int)((const long long*)batch)[i] : ((const int*)batch)[i];
        g_batch[i] = b;
        atomicAdd(&g_cnt[b], 1.f);
    }
}

// Single-block scan + dinv.
__global__ void k_scan() {
    __shared__ int sh[1024];
    int t = threadIdx.x;
    const int C = (NN + 1023) / 1024;
    int base = t * C;
    int sum = 0;
    for (int j = 0; j < C; j++) {
        int i = base + j;
        if (i < NN) sum += g_deg[i];
    }
    sh[t] = sum;
    __syncthreads();
    for (int d = 1; d < 1024; d <<= 1) {
        int v = (t >= d) ? sh[t - d] : 0;
        __syncthreads();
        sh[t] += v;
        __syncthreads();
    }
    int run = sh[t] - sum;
    if (t == 0) g_offs[0] = 0;
    for (int j = 0; j < C; j++) {
        int i = base + j;
        if (i < NN) {
            int d = g_deg[i];
            g_cursor[i] = run;
            run += d;
            g_offs[i + 1] = run;
            g_dinv[i] = rsqrtf((float)(d + 1));
        }
    }
}

__global__ void k_fill(const void* __restrict__ ei) {
    int i = blockIdx.x * blockDim.x + threadIdx.x;
    if (i < EE) {
        int s, d;
        if (g_is64) {
            const long long* p = (const long long*)ei;
            s = (int)p[i]; d = (int)p[EE + i];
        } else {
            const int* p = (const int*)ei;
            s = p[i]; d = p[EE + i];
        }
        int slot = atomicAdd(&g_cursor[d], 1);
        g_perm[slot] = s;
    }
}

// ---------------- WMMA GEMM (+optional fused GIN gather) -------------------------
// C[M,128] = act((A[M,128] @ W[128,128]) * scale? + bias?), split-bf16 (3 products),
// fp32 accumulate. 256 threads = 8 warps; warp tile = 64 rows x 16 cols: per k-step
// each warp loads only 2 B fragments (hi/lo, L1-resident W) + 8 A fragments (LDSM
// from smem). fused=1: A row = h[node] + sum_nbr h[nbr] (GIN aggregation).
#define AST 136     // A smem stride (bf16 elements)
#define CST 132     // epilogue smem stride (floats)

__global__ void __launch_bounds__(256)
k_wmma(const float* __restrict__ A, int widx,
       const float* __restrict__ bias, const float* __restrict__ scale,
       float* __restrict__ C, int M, int fused, int relu) {
    __shared__ __align__(16) char sm[64 * AST * 2 * 2];   // 34816 B
    __nv_bfloat16* sa_hi = (__nv_bfloat16*)sm;
    __nv_bfloat16* sa_lo = (__nv_bfloat16*)(sm + 64 * AST * 2);
    int tid = threadIdx.x, wid = tid >> 5, lane = tid & 31;
    int m0 = blockIdx.x * 64;

    // ---- A fill (split to bf16 hi/lo) ----
    if (!fused) {
        const float4* A4 = (const float4*)A;
#pragma unroll
        for (int i = 0; i < 8; i++) {
            int idx = tid + i * 256;           // 2048 float4 slots
            int r = idx >> 5, q = idx & 31;
            float4 v = (m0 + r < M) ? __ldg(&A4[(m0 + r) * 32 + q]) : f4zero();
            uint2 hi, lo;
            split4(v, hi, lo);
            *(uint2*)(sa_hi + r * AST + q * 4) = hi;
            *(uint2*)(sa_lo + r * AST + q * 4) = lo;
        }
    } else {
        const float4* h4 = (const float4*)A;
#pragma unroll 1
        for (int rr = 0; rr < 8; rr++) {
            int r = wid * 8 + rr;              // 8 warps x 8 rows = 64
            int node = m0 + r;
            float4 acc = f4zero();
            if (node < M) {
                acc = h4[node * 32 + lane];
                int s0 = g_offs[node], s1 = g_offs[node + 1];
                int j = s0;
                for (; j + 3 < s1; j += 4) {
                    int n0 = g_perm[j], n1 = g_perm[j + 1], n2 = g_perm[j + 2], n3 = g_perm[j + 3];
                    float4 u0 = h4[n0 * 32 + lane];
                    float4 u1 = h4[n1 * 32 + lane];
                    float4 u2 = h4[n2 * 32 + lane];
                    float4 u3 = h4[n3 * 32 + lane];
                    acc.x += (u0.x + u1.x) + (u2.x + u3.x);
                    acc.y += (u0.y + u1.y) + (u2.y + u3.y);
                    acc.z += (u0.z + u1.z) + (u2.z + u3.z);
                    acc.w += (u0.w + u1.w) + (u2.w + u3.w);
                }
                for (; j < s1; j++) {
                    float4 u = h4[g_perm[j] * 32 + lane];
                    acc.x += u.x; acc.y += u.y; acc.z += u.z; acc.w += u.w;
                }
            }
            uint2 hi, lo;
            split4(acc, hi, lo);
            *(uint2*)(sa_hi + r * AST + lane * 4) = hi;
            *(uint2*)(sa_lo + r * AST + lane * 4) = lo;
        }
    }
    __syncthreads();

    // ---- tensor phase: warp wid owns cols wid*16..+15, all 64 rows --------------
    wmma::fragment<wmma::accumulator, 16, 16, 16, float> facc[4];
#pragma unroll
    for (int r = 0; r < 4; r++) wmma::fill_fragment(facc[r], 0.f);

    const __nv_bfloat16* Bh = g_Wh + widx * 16384 + wid * 16;
    const __nv_bfloat16* Bl = g_Wl + widx * 16384 + wid * 16;

#pragma unroll 1
    for (int k = 0; k < 8; k++) {
        wmma::fragment<wmma::matrix_b, 16, 16, 16, __nv_bfloat16, wmma::row_major> bh, bl;
        wmma::load_matrix_sync(bh, Bh + (k * 16) * 128, 128);
        wmma::load_matrix_sync(bl, Bl + (k * 16) * 128, 128);
#pragma unroll
        for (int r = 0; r < 4; r++) {
            wmma::fragment<wmma::matrix_a, 16, 16, 16, __nv_bfloat16, wmma::row_major> ah, al;
            wmma::load_matrix_sync(ah, sa_hi + (r * 16) * AST + k * 16, AST);
            wmma::load_matrix_sync(al, sa_lo + (r * 16) * AST + k * 16, AST);
            wmma::mma_sync(facc[r], ah, bh, facc[r]);
            wmma::mma_sync(facc[r], ah, bl, facc[r]);
            wmma::mma_sync(facc[r], al, bh, facc[r]);
        }
    }

    // ---- epilogue via smem (reuse A area) ----
    __syncthreads();
    float* cs = (float*)sm;
#pragma unroll
    for (int r = 0; r < 4; r++)
        wmma::store_matrix_sync(cs + (r * 16) * CST + wid * 16,
                                facc[r], CST, wmma::mem_row_major);
    __syncthreads();

    const float4* b4p = (const float4*)bias;
    float4* C4 = (float4*)C;
#pragma unroll
    for (int i = 0; i < 8; i++) {
        int idx = tid + i * 256;
        int r = idx >> 5, q = idx & 31;
        int grow = m0 + r;
        if (grow < M) {
            float4 o = *(float4*)(cs + r * CST + q * 4);
            float s = scale ? scale[grow] : 1.f;
            float4 bb = f4zero();
            if (bias) bb = b4p[q];
            o.x = fmaf(o.x, s, bb.x); o.y = fmaf(o.y, s, bb.y);
            o.z = fmaf(o.z, s, bb.z); o.w = fmaf(o.w, s, bb.w);
            if (relu) {
                o.x = fmaxf(o.x, 0.f); o.y = fmaxf(o.y, 0.f);
                o.z = fmaxf(o.z, 0.f); o.w = fmaxf(o.w, 0.f);
            }
            C4[grow * 32 + q] = o;
        }
    }
}

// ---------------- GCN aggregation (standalone; h pre-scaled by dinv) -------------
__global__ void k_gcn_agg(const float* __restrict__ h, const float* __restrict__ b0,
                          float* __restrict__ out) {
    int node = blockIdx.x * 8 + (threadIdx.x >> 5);
    if (node >= NN) return;
    int lane = threadIdx.x & 31;
    const float4* h4 = (const float4*)h;

    float4 acc = h4[node * 32 + lane];
    int s0 = g_offs[node], s1 = g_offs[node + 1];
    int j = s0;
    for (; j + 3 < s1; j += 4) {
        int n0 = g_perm[j], n1 = g_perm[j + 1], n2 = g_perm[j + 2], n3 = g_perm[j + 3];
        float4 u0 = h4[n0 * 32 + lane];
        float4 u1 = h4[n1 * 32 + lane];
        float4 u2 = h4[n2 * 32 + lane];
        float4 u3 = h4[n3 * 32 + lane];
        acc.x += (u0.x + u1.x) + (u2.x + u3.x);
        acc.y += (u0.y + u1.y) + (u2.y + u3.y);
        acc.z += (u0.z + u1.z) + (u2.z + u3.z);
        acc.w += (u0.w + u1.w) + (u2.w + u3.w);
    }
    for (; j < s1; j++) {
        float4 u = h4[g_perm[j] * 32 + lane];
        acc.x += u.x; acc.y += u.y; acc.z += u.z; acc.w += u.w;
    }
    float di = g_dinv[node];
    float4 b = ((const float4*)b0)[lane];
    float4 o;
    o.x = fmaxf(fmaf(di, acc.x, b.x), 0.f);
    o.y = fmaxf(fmaf(di, acc.y, b.y), 0.f);
    o.z = fmaxf(fmaf(di, acc.z, b.z), 0.f);
    o.w = fmaxf(fmaf(di, acc.w, b.w), 0.f);
    ((float4*)out)[node * 32 + lane] = o;
}

// ---------------- mean pool: sorted batch -> run-accumulate, few atomics ---------
#define POOL_NODES 128
__global__ void k_pool(const float* __restrict__ h) {
    __shared__ int sb[POOL_NODES];
    int c = threadIdx.x;
    int n0 = blockIdx.x * POOL_NODES;
    int nend = n0 + POOL_NODES; if (nend > NN) nend = NN;
    for (int i = n0 + c; i < nend; i += 128) sb[i - n0] = g_batch[i];
    __syncthreads();

    float acc = 0.f;
    int cur = sb[0];
    for (int n = n0; n < nend; n++) {
        int g = sb[n - n0];
        if (g != cur) {
            atomicAdd(&g_pool[cur * HH + c], acc);
            acc = 0.f; cur = g;
        }
        acc += h[n * HH + c];
    }
    atomicAdd(&g_pool[cur * HH + c], acc);
}

// ---------------- head MLP ----------------
__global__ void k_head1(const float* __restrict__ Wh1, const float* __restrict__ bh1) {
    int g = blockIdx.x, c = threadIdx.x;
    float inv = 1.f / fmaxf(g_cnt[g], 1.f);
    float acc = bh1[c];
    const float* pr = &g_pool[g * HH];
#pragma unroll 8
    for (int k = 0; k < HH; k++)
        acc = fmaf(pr[k] * inv, __ldg(&Wh1[k * NHID + c]), acc);
    g_hid[g * NHID + c] = fmaxf(acc, 0.f);
}

__global__ void k_head2(const float* __restrict__ Wh2, const float* __restrict__ bh2,
                        float* __restrict__ out) {
    int g = blockIdx.x, c = threadIdx.x;
    float acc = bh2[c];
    const float* hr = &g_hid[g * NHID];
#pragma unroll 8
    for (int k = 0; k < NHID; k++)
        acc = fmaf(hr[k], __ldg(&Wh2[k * NOUT + c]), acc);
    out[g * NOUT + c] = acc;
}

// ---------------- launch ----------------
extern "C" void kernel_launch(void* const* d_in, const int* in_sizes, int n_in,
                              void* d_out, int out_size) {
    (void)in_sizes; (void)n_in; (void)out_size;
    const float* x   = (const float*)d_in[0];
    const void*  ei  = d_in[1];
    const void*  bat = d_in[2];
    const float* W0  = (const float*)d_in[3];
    const float* b0  = (const float*)d_in[4];
    const float* Wg1 = (const float*)d_in[5];
    const float* bg1 = (const float*)d_in[6];
    const float* Wg2 = (const float*)d_in[7];
    const float* bg2 = (const float*)d_in[8];
    const float* Wh1 = (const float*)d_in[9];
    const float* bh1 = (const float*)d_in[10];
    const float* Wh2 = (const float*)d_in[11];
    const float* bh2 = (const float*)d_in[12];
    float* out = (float*)d_out;

    float *bufA, *bufB, *dinv;
    cudaGetSymbolAddress((void**)&bufA, g_bufA);
    cudaGetSymbolAddress((void**)&bufB, g_bufB);
    cudaGetSymbolAddress((void**)&dinv, g_dinv);

    const int TB = 256;
    int mma_blocks = (NN + 63) / 64;     // 782
    int agg_blocks = (NN + 7) / 8;

    // 0..2: setup (+weight bf16 prep), count, scan
    k_setup<<<388, TB>>>((const unsigned int*)ei, W0, Wg1, Wg2);
    k_count<<<(EE + TB - 1) / TB, TB>>>(ei, bat);
    k_scan<<<1, 1024>>>();
    // 3: GCN transform via WMMA, row-scaled by dinv  (PROFILED LAUNCH)
    k_wmma<<<mma_blocks, 256>>>(x, 0, nullptr, dinv, bufA, NN, 0, 0);
    // 4: CSR bucket fill
    k_fill<<<(EE + TB - 1) / TB, TB>>>(ei);
    // 5: GCN aggregation (+bias+relu)
    k_gcn_agg<<<agg_blocks, 256>>>(bufA, b0, bufB);
    // 6: GIN layer 1 (fused gather + WMMA + bias + relu)
    k_wmma<<<mma_blocks, 256>>>(bufB, 1, bg1, nullptr, bufA, NN, 1, 1);
    // 7: GIN layer 2
    k_wmma<<<mma_blocks, 256>>>(bufA, 2, bg2, nullptr, bufB, NN, 1, 1);
    // 8-10: pool + head
    k_pool<<<(NN + POOL_NODES - 1) / POOL_NODES, 128>>>(bufB);
    k_head1<<<GG, NHID>>>(Wh1, bh1);
    k_head2<<<GG, NOUT>>>(Wh2, bh2, out);
}